// round 1
// baseline (speedup 1.0000x reference)
#include <cuda_runtime.h>
#include <math.h>

#define TT 2048
#define WDIM 768
#define HH 512
#define G4 2048      // 4*H
#define NCAT 5
#define STARTT 3
#define ENDT 4
#define NC 32        // CTAs per direction in recurrence
#define MH 16        // h lanes per CTA (512/32)

// -------- scratch (static device globals; no allocation) --------
__device__ float Zbuf[2][(size_t)TT * G4];   // z_in per direction (32 MB)
__device__ float Hcat[(size_t)TT * 2 * HH];  // [t][h_f | h_b] (8 MB)
__device__ float hping[2][2][HH];            // [dir][phase][H]
__device__ int   stepcnt[2][TT];
__device__ float feats_g[TT * NCAT];

// ================= zero state (per graph replay) =================
__global__ void zero_state() {
    int i = blockIdx.x * blockDim.x + threadIdx.x;
    if (i < 2 * TT) ((int*)stepcnt)[i] = 0;
    if (i < 2 * 2 * HH) ((float*)hping)[i] = 0.f;
}

// ================= Kernel A: gather + z_in GEMM =================
// Z[t][g] = emb[sent[t]] . Wih[g] + bih[g] + bhh[g]
#define BM 128
#define BN 128
#define BK 16

__global__ __launch_bounds__(256, 1) void gemm_zin(
    const int* __restrict__ sent, const float* __restrict__ emb,
    const float* __restrict__ WihF, const float* __restrict__ WihB,
    const float* __restrict__ bihF, const float* __restrict__ bhhF,
    const float* __restrict__ bihB, const float* __restrict__ bhhB)
{
    const int dir = blockIdx.z;
    const float* __restrict__ Wih = dir ? WihB : WihF;
    const float* __restrict__ b1  = dir ? bihB : bihF;
    const float* __restrict__ b2  = dir ? bhhB : bhhF;
    float* __restrict__ Z = Zbuf[dir];

    __shared__ float As[BK][BM + 4];
    __shared__ float Bs[BK][BN + 4];
    __shared__ int   sidx[BM];

    const int tid = threadIdx.x;
    const int m0 = blockIdx.y * BM;
    const int n0 = blockIdx.x * BN;

    if (tid < BM) sidx[tid] = sent[m0 + tid];
    __syncthreads();

    const int la_r = tid >> 2;          // 0..63
    const int la_k = (tid & 3) * 4;     // 0,4,8,12
    const int tx = tid & 15, ty = tid >> 4;

    float acc[8][8];
    #pragma unroll
    for (int i = 0; i < 8; i++)
        #pragma unroll
        for (int j = 0; j < 8; j++) acc[i][j] = 0.f;

    for (int k0 = 0; k0 < WDIM; k0 += BK) {
        #pragma unroll
        for (int i = 0; i < 2; i++) {
            int m = la_r + i * 64;
            float4 v = *reinterpret_cast<const float4*>(
                &emb[(size_t)sidx[m] * WDIM + k0 + la_k]);
            As[la_k + 0][m] = v.x; As[la_k + 1][m] = v.y;
            As[la_k + 2][m] = v.z; As[la_k + 3][m] = v.w;
        }
        #pragma unroll
        for (int i = 0; i < 2; i++) {
            int n = la_r + i * 64;
            float4 v = *reinterpret_cast<const float4*>(
                &Wih[(size_t)(n0 + n) * WDIM + k0 + la_k]);
            Bs[la_k + 0][n] = v.x; Bs[la_k + 1][n] = v.y;
            Bs[la_k + 2][n] = v.z; Bs[la_k + 3][n] = v.w;
        }
        __syncthreads();

        #pragma unroll
        for (int k = 0; k < BK; k++) {
            float a[8], b[8];
            float4 a0 = *reinterpret_cast<const float4*>(&As[k][ty * 8]);
            float4 a1 = *reinterpret_cast<const float4*>(&As[k][ty * 8 + 4]);
            float4 b0 = *reinterpret_cast<const float4*>(&Bs[k][tx * 8]);
            float4 b1v = *reinterpret_cast<const float4*>(&Bs[k][tx * 8 + 4]);
            a[0]=a0.x; a[1]=a0.y; a[2]=a0.z; a[3]=a0.w;
            a[4]=a1.x; a[5]=a1.y; a[6]=a1.z; a[7]=a1.w;
            b[0]=b0.x; b[1]=b0.y; b[2]=b0.z; b[3]=b0.w;
            b[4]=b1v.x; b[5]=b1v.y; b[6]=b1v.z; b[7]=b1v.w;
            #pragma unroll
            for (int i = 0; i < 8; i++)
                #pragma unroll
                for (int j = 0; j < 8; j++)
                    acc[i][j] = fmaf(a[i], b[j], acc[i][j]);
        }
        __syncthreads();
    }

    #pragma unroll
    for (int i = 0; i < 8; i++) {
        int m = m0 + ty * 8 + i;
        #pragma unroll
        for (int j = 0; j < 8; j++) {
            int n = n0 + tx * 8 + j;
            Z[(size_t)m * G4 + n] = acc[i][j] + b1[n] + b2[n];
        }
    }
}

// ================= Kernel B: BiLSTM recurrence (persistent) =================
__device__ __forceinline__ float sigm(float x) { return 1.f / (1.f + expf(-x)); }

__global__ __launch_bounds__(512, 1) void lstm_rec(
    const float* __restrict__ WhhF, const float* __restrict__ WhhB)
{
    const int d = blockIdx.x / NC;
    const int k = blockIdx.x % NC;
    const float* __restrict__ Whh = d ? WhhB : WhhF;
    const float* __restrict__ Z = Zbuf[d];

    const int tid = threadIdx.x;
    const int r = tid >> 3;          // 0..63: gate-row within CTA
    const int sub = tid & 7;         // 8 threads per row
    const int gate = r >> 4;         // 0:i 1:f 2:g 3:o
    const int jj = r & 15;
    const int grow = gate * HH + k * MH + jj;   // global gate row

    // Whh slice in registers: w[e] multiplies h[e*8+sub]
    float w[64];
    #pragma unroll
    for (int e = 0; e < 64; e++)
        w[e] = Whh[(size_t)grow * HH + e * 8 + sub];

    __shared__ float h_s[HH];
    __shared__ float gacc[64];
    __shared__ float c_s[MH];
    if (tid < MH) c_s[tid] = 0.f;

    volatile int* cnt = &stepcnt[d][0];

    for (int s = 0; s < TT; s++) {
        const int t = d ? (TT - 1 - s) : s;
        if (s > 0) {
            if (tid == 0) { while (cnt[s - 1] < NC) { } }
            __syncthreads();
            __threadfence();   // acquire side
        }
        h_s[tid] = __ldcg(&hping[d][s & 1][tid]);   // step 0 reads zeros
        __syncthreads();

        float acc = 0.f;
        #pragma unroll
        for (int e = 0; e < 64; e++)
            acc = fmaf(w[e], h_s[e * 8 + sub], acc);
        acc += __shfl_xor_sync(0xffffffffu, acc, 4);
        acc += __shfl_xor_sync(0xffffffffu, acc, 2);
        acc += __shfl_xor_sync(0xffffffffu, acc, 1);
        if (sub == 0)
            gacc[r] = acc + Z[(size_t)t * G4 + grow];
        __syncthreads();

        if (tid < MH) {
            float gi = gacc[tid], gf = gacc[16 + tid],
                  gg = gacc[32 + tid], go = gacc[48 + tid];
            float c = sigm(gf) * c_s[tid] + sigm(gi) * tanhf(gg);
            c_s[tid] = c;
            float h = sigm(go) * tanhf(c);
            __stcg(&hping[d][(s + 1) & 1][k * MH + tid], h);
            Hcat[(size_t)t * (2 * HH) + d * HH + k * MH + tid] = h;
        }
        __syncthreads();
        if (tid == 0) {
            __threadfence();   // release side
            atomicAdd(&stepcnt[d][s], 1);
        }
    }
}

// ================= Kernel C: FC feats =================
__global__ __launch_bounds__(256) void fc_feats(
    const float* __restrict__ fc_w, const float* __restrict__ fc_b)
{
    __shared__ float wsh[NCAT][2 * HH];
    for (int i = threadIdx.x; i < NCAT * 2 * HH; i += 256)
        wsh[i / (2 * HH)][i % (2 * HH)] = fc_w[i];
    __syncthreads();

    const int warp = threadIdx.x >> 5, lane = threadIdx.x & 31;
    const int t = blockIdx.x * 8 + warp;

    float a[NCAT];
    #pragma unroll
    for (int c = 0; c < NCAT; c++) a[c] = 0.f;
    for (int e = lane; e < 2 * HH; e += 32) {
        float x = Hcat[(size_t)t * 2 * HH + e];
        #pragma unroll
        for (int c = 0; c < NCAT; c++) a[c] = fmaf(x, wsh[c][e], a[c]);
    }
    #pragma unroll
    for (int c = 0; c < NCAT; c++) {
        #pragma unroll
        for (int o = 16; o > 0; o >>= 1)
            a[c] += __shfl_xor_sync(0xffffffffu, a[c], o);
    }
    if (lane == 0) {
        #pragma unroll
        for (int c = 0; c < NCAT; c++)
            feats_g[t * NCAT + c] = a[c] + fc_b[c];
    }
}

// ================= Kernel D: Viterbi + backtrack + output =================
__global__ __launch_bounds__(32) void viterbi(
    const float* __restrict__ trans, float* __restrict__ out)
{
    __shared__ int par[(TT - 1) * NCAT];   // ~41 KB
    const int tid = threadIdx.x;

    float trow[NCAT];
    float layer = 0.f;
    if (tid < NCAT) {
        #pragma unroll
        for (int j = 0; j < NCAT; j++) trow[j] = trans[tid * NCAT + j];
        layer = feats_g[tid] + trans[tid * NCAT + STARTT];
    }

    for (int t = 1; t < TT; t++) {
        float lj[NCAT];
        #pragma unroll
        for (int j = 0; j < NCAT; j++)
            lj[j] = __shfl_sync(0xffffffffu, layer, j);
        if (tid < NCAT) {
            float best = trow[0] + lj[0];
            int barg = 0;
            #pragma unroll
            for (int j = 1; j < NCAT; j++) {
                float sc = trow[j] + lj[j];
                if (sc > best) { best = sc; barg = j; }   // strict > = first-max tiebreak
            }
            layer = best + feats_g[t * NCAT + tid];
            par[(t - 1) * NCAT + tid] = barg;
        }
    }

    __shared__ float finsh[NCAT];
    if (tid < NCAT) finsh[tid] = layer + trans[ENDT * NCAT + tid];
    __syncthreads();

    if (tid == 0) {
        int idx = 0; float best = finsh[0];
        #pragma unroll
        for (int i = 1; i < NCAT; i++)
            if (finsh[i] > best) { best = finsh[i]; idx = i; }
        out[TT] = best;
        out[TT - 1] = (float)idx;
        for (int t = TT - 2; t >= 0; t--) {
            idx = par[t * NCAT + idx];
            out[t] = (float)idx;
        }
    }
}

// ================= launch =================
extern "C" void kernel_launch(void* const* d_in, const int* in_sizes, int n_in,
                              void* d_out, int out_size)
{
    const int*   sent  = (const int*)d_in[0];
    const float* emb   = (const float*)d_in[1];
    const float* WihF  = (const float*)d_in[2];
    const float* WhhF  = (const float*)d_in[3];
    const float* bihF  = (const float*)d_in[4];
    const float* bhhF  = (const float*)d_in[5];
    const float* WihB  = (const float*)d_in[6];
    const float* WhhB  = (const float*)d_in[7];
    const float* bihB  = (const float*)d_in[8];
    const float* bhhB  = (const float*)d_in[9];
    const float* fc_w  = (const float*)d_in[10];
    const float* fc_b  = (const float*)d_in[11];
    const float* trans = (const float*)d_in[12];
    float* out = (float*)d_out;

    zero_state<<<16, 256>>>();

    dim3 g(G4 / BN, TT / BM, 2);
    gemm_zin<<<g, 256>>>(sent, emb, WihF, WihB, bihF, bhhF, bihB, bhhB);

    lstm_rec<<<2 * NC, 512>>>(WhhF, WhhB);

    fc_feats<<<TT / 8, 256>>>(fc_w, fc_b);

    viterbi<<<1, 32>>>(trans, out);
}